// round 1
// baseline (speedup 1.0000x reference)
#include <cuda_runtime.h>
#include <cuda_bf16.h>

#define NB 64      // batch
#define TT 512     // timesteps
#define DD 512     // input size
#define HH 512     // hidden size
#define SCAN_CTAS 32
#define SCAN_NT (HH / SCAN_CTAS)   // 16 hidden columns per CTA

// ---------------- scratch (device globals; no allocation allowed) ----------
__device__ __align__(16) __nv_bfloat16 g_hh[2][NB * HH];  // h hi, double buffered
__device__ __align__(16) __nv_bfloat16 g_hl[2][NB * HH];  // h lo
__device__ unsigned g_bar_gen = 0;
__device__ unsigned g_bar_cnt = 0;

// ---------------- helpers --------------------------------------------------
__device__ __forceinline__ void split2(float v, __nv_bfloat16 &hi, __nv_bfloat16 &lo) {
    hi = __float2bfloat16(v);
    lo = __float2bfloat16(v - __bfloat162float(hi));
}

__device__ __forceinline__ void mma_bf16(float *c, const unsigned *a, const unsigned *b) {
    asm volatile(
        "mma.sync.aligned.m16n8k16.row.col.f32.bf16.bf16.f32 "
        "{%0,%1,%2,%3}, {%4,%5,%6,%7}, {%8,%9}, {%0,%1,%2,%3};\n"
        : "+f"(c[0]), "+f"(c[1]), "+f"(c[2]), "+f"(c[3])
        : "r"(a[0]), "r"(a[1]), "r"(a[2]), "r"(a[3]),
          "r"(b[0]), "r"(b[1]));
}

__device__ __forceinline__ float fast_tanh(float x) {
    // tanh(x) = 1 - 2/(exp(2x)+1); handles +/-inf saturation correctly.
    float e = __expf(2.0f * x);
    return 1.0f - __fdividef(2.0f, e + 1.0f);
}

// ---------------- kernel 1: xWx = x @ Wx + b  -> out ------------------------
// C[32768,512] = X[32768,512] @ Wx[512,512], split-bf16 (3 MMAs) for ~fp32 acc.
// CTA tile 128x64, BK=32, 256 threads (8 warps: 4(m) x 2(n), warp tile 32x32).
__global__ __launch_bounds__(256) void gemm_xwx_kernel(
    const float *__restrict__ x, const float *__restrict__ Wx,
    const float *__restrict__ b, float *__restrict__ out) {

    __shared__ __align__(16) __nv_bfloat16 Ah[128 * 40];
    __shared__ __align__(16) __nv_bfloat16 Al[128 * 40];
    __shared__ __align__(16) __nv_bfloat16 Bh[64 * 40];
    __shared__ __align__(16) __nv_bfloat16 Bl[64 * 40];

    const int tid  = threadIdx.x;
    const int warp = tid >> 5;
    const int lane = tid & 31;
    const int g    = lane >> 2;   // 0..7
    const int tg   = lane & 3;    // 0..3
    const int wm   = warp >> 1;   // 0..3
    const int wn   = warp & 1;    // 0..1
    const int row0 = blockIdx.x * 128;
    const int col0 = blockIdx.y * 64;

    float acc[2][4][4];
#pragma unroll
    for (int mt = 0; mt < 2; mt++)
#pragma unroll
        for (int nt = 0; nt < 4; nt++)
#pragma unroll
            for (int i = 0; i < 4; i++) acc[mt][nt][i] = 0.0f;

    for (int k0 = 0; k0 < DD; k0 += 32) {
        __syncthreads();
        // load + split A tile: 128 x 32
#pragma unroll
        for (int i = 0; i < 16; i++) {
            int idx = tid + i * 256;
            int r = idx >> 5, c = idx & 31;
            float v = x[(size_t)(row0 + r) * DD + k0 + c];
            __nv_bfloat16 hi, lo; split2(v, hi, lo);
            Ah[r * 40 + c] = hi; Al[r * 40 + c] = lo;
        }
        // load + split B tile: 32 x 64, stored transposed [n][k]
#pragma unroll
        for (int i = 0; i < 8; i++) {
            int idx = tid + i * 256;
            int nn = idx & 63, kk = idx >> 6;
            float v = Wx[(size_t)(k0 + kk) * HH + col0 + nn];
            __nv_bfloat16 hi, lo; split2(v, hi, lo);
            Bh[nn * 40 + kk] = hi; Bl[nn * 40 + kk] = lo;
        }
        __syncthreads();

#pragma unroll
        for (int ks = 0; ks < 2; ks++) {
            const int kb = ks * 16;
            unsigned ah[2][4], al[2][4], bh[4][2], bl[4][2];
#pragma unroll
            for (int mt = 0; mt < 2; mt++) {
                int r = wm * 32 + mt * 16 + g;
                ah[mt][0] = *(const unsigned *)&Ah[r * 40 + kb + tg * 2];
                ah[mt][1] = *(const unsigned *)&Ah[(r + 8) * 40 + kb + tg * 2];
                ah[mt][2] = *(const unsigned *)&Ah[r * 40 + kb + 8 + tg * 2];
                ah[mt][3] = *(const unsigned *)&Ah[(r + 8) * 40 + kb + 8 + tg * 2];
                al[mt][0] = *(const unsigned *)&Al[r * 40 + kb + tg * 2];
                al[mt][1] = *(const unsigned *)&Al[(r + 8) * 40 + kb + tg * 2];
                al[mt][2] = *(const unsigned *)&Al[r * 40 + kb + 8 + tg * 2];
                al[mt][3] = *(const unsigned *)&Al[(r + 8) * 40 + kb + 8 + tg * 2];
            }
#pragma unroll
            for (int nt = 0; nt < 4; nt++) {
                int n = wn * 32 + nt * 8 + g;
                bh[nt][0] = *(const unsigned *)&Bh[n * 40 + kb + tg * 2];
                bh[nt][1] = *(const unsigned *)&Bh[n * 40 + kb + 8 + tg * 2];
                bl[nt][0] = *(const unsigned *)&Bl[n * 40 + kb + tg * 2];
                bl[nt][1] = *(const unsigned *)&Bl[n * 40 + kb + 8 + tg * 2];
            }
#pragma unroll
            for (int mt = 0; mt < 2; mt++)
#pragma unroll
                for (int nt = 0; nt < 4; nt++) {
                    mma_bf16(acc[mt][nt], ah[mt], bh[nt]);  // Ah*Bh
                    mma_bf16(acc[mt][nt], ah[mt], bl[nt]);  // Ah*Bl
                    mma_bf16(acc[mt][nt], al[mt], bh[nt]);  // Al*Bh
                }
        }
    }

    // epilogue: + bias, write fp32
#pragma unroll
    for (int mt = 0; mt < 2; mt++)
#pragma unroll
        for (int nt = 0; nt < 4; nt++) {
            int r = row0 + wm * 32 + mt * 16 + g;
            int c = col0 + wn * 32 + nt * 8 + tg * 2;
            float b0 = b[c], b1 = b[c + 1];
            out[(size_t)r * HH + c]             = acc[mt][nt][0] + b0;
            out[(size_t)r * HH + c + 1]         = acc[mt][nt][1] + b1;
            out[(size_t)(r + 8) * HH + c]       = acc[mt][nt][2] + b0;
            out[(size_t)(r + 8) * HH + c + 1]   = acc[mt][nt][3] + b1;
        }
}

// ---------------- kernel 2: persistent recurrent scan ----------------------
// 32 CTAs x 256 threads. CTA owns 16 hidden columns. Per step:
//   stage h_{t-1} (hi/lo bf16) into SMEM -> 3-way split MMA vs resident Wh slice
//   -> + xwx (in d_out) -> tanh -> write fp32 to d_out + split bf16 to g_h.
// Grid sync via generation-counter barrier (all 32 CTAs trivially co-resident).

__device__ __forceinline__ void grid_barrier() {
    __syncthreads();
    if (threadIdx.x == 0) {
        volatile unsigned *genp = &g_bar_gen;
        unsigned target = *genp + 1;
        __threadfence();
        if (atomicAdd(&g_bar_cnt, 1) == SCAN_CTAS - 1) {
            g_bar_cnt = 0;
            __threadfence();
            atomicAdd(&g_bar_gen, 1);
        } else {
            while (*genp < target) { }
        }
        __threadfence();
    }
    __syncthreads();
}

#define HSTRIDE 520  // 512 + 8 pad (conflict-free fragment reads, 16B row align)

__global__ __launch_bounds__(256) void rnn_scan_kernel(
    const float *__restrict__ h0, const float *__restrict__ Wh,
    float *__restrict__ out) {

    extern __shared__ __nv_bfloat16 smem[];
    __nv_bfloat16 *Hh  = smem;                       // 64 x 520
    __nv_bfloat16 *Hl  = Hh + 64 * HSTRIDE;          // 64 x 520
    __nv_bfloat16 *Wsh = Hl + 64 * HSTRIDE;          // 16 x 520
    __nv_bfloat16 *Wsl = Wsh + SCAN_NT * HSTRIDE;    // 16 x 520

    const int tid  = threadIdx.x;
    const int warp = tid >> 5;
    const int lane = tid & 31;
    const int g    = lane >> 2;
    const int tg   = lane & 3;
    const int cb   = blockIdx.x * SCAN_NT;          // column base of this CTA
    const int mtile = (warp >> 1) << 4;             // 0,16,32,48
    const int ntile = (warp & 1) << 3;              // 0,8

    // resident Wh slice: Wsh[n][k] = Wh[k][cb+n], split hi/lo
    for (int idx = tid; idx < HH * SCAN_NT; idx += 256) {
        int n = idx & (SCAN_NT - 1), k = idx >> 4;
        float v = Wh[(size_t)k * HH + cb + n];
        __nv_bfloat16 hi, lo; split2(v, hi, lo);
        Wsh[n * HSTRIDE + k] = hi; Wsl[n * HSTRIDE + k] = lo;
    }
    // init h0 slice into buffer 0
    for (int idx = tid; idx < NB * SCAN_NT; idx += 256) {
        int m = idx >> 4, n = idx & (SCAN_NT - 1);
        float v = h0[(size_t)m * HH + cb + n];
        __nv_bfloat16 hi, lo; split2(v, hi, lo);
        g_hh[0][m * HH + cb + n] = hi;
        g_hl[0][m * HH + cb + n] = lo;
    }
    __threadfence();
    grid_barrier();

    for (int t = 0; t < TT; t++) {
        const int rb = t & 1;
        const int wb = rb ^ 1;

        // stage full h_{t-1} (hi+lo) into SMEM, 16B vectors
#pragma unroll
        for (int i = 0; i < 16; i++) {
            int idx = tid + i * 256;           // 4096 uint4 per buffer
            int r = idx >> 6, c = idx & 63;
            ((uint4 *)(Hh + r * HSTRIDE))[c] = ((const uint4 *)(g_hh[rb] + r * HH))[c];
            ((uint4 *)(Hl + r * HSTRIDE))[c] = ((const uint4 *)(g_hl[rb] + r * HH))[c];
        }
        __syncthreads();

        float c4[4] = {0.f, 0.f, 0.f, 0.f};
        const int rA = mtile + g;
        const int nB = ntile + g;
#pragma unroll 4
        for (int k0 = 0; k0 < HH; k0 += 16) {
            unsigned ah[4], al[4], bh[2], bl[2];
            ah[0] = *(const unsigned *)&Hh[rA * HSTRIDE + k0 + tg * 2];
            ah[1] = *(const unsigned *)&Hh[(rA + 8) * HSTRIDE + k0 + tg * 2];
            ah[2] = *(const unsigned *)&Hh[rA * HSTRIDE + k0 + 8 + tg * 2];
            ah[3] = *(const unsigned *)&Hh[(rA + 8) * HSTRIDE + k0 + 8 + tg * 2];
            al[0] = *(const unsigned *)&Hl[rA * HSTRIDE + k0 + tg * 2];
            al[1] = *(const unsigned *)&Hl[(rA + 8) * HSTRIDE + k0 + tg * 2];
            al[2] = *(const unsigned *)&Hl[rA * HSTRIDE + k0 + 8 + tg * 2];
            al[3] = *(const unsigned *)&Hl[(rA + 8) * HSTRIDE + k0 + 8 + tg * 2];
            bh[0] = *(const unsigned *)&Wsh[nB * HSTRIDE + k0 + tg * 2];
            bh[1] = *(const unsigned *)&Wsh[nB * HSTRIDE + k0 + 8 + tg * 2];
            bl[0] = *(const unsigned *)&Wsl[nB * HSTRIDE + k0 + tg * 2];
            bl[1] = *(const unsigned *)&Wsl[nB * HSTRIDE + k0 + 8 + tg * 2];
            mma_bf16(c4, ah, bh);
            mma_bf16(c4, ah, bl);
            mma_bf16(c4, al, bh);
        }

        // epilogue: + xwx (already in out), tanh, write fp32 + split h
        {
            const int ccol = cb + ntile + tg * 2;
#pragma unroll
            for (int half = 0; half < 2; half++) {
                int m = mtile + g + half * 8;
                size_t base = ((size_t)m * TT + t) * HH;
                float v0 = c4[half * 2 + 0] + out[base + ccol];
                float v1 = c4[half * 2 + 1] + out[base + ccol + 1];
                float hv0 = fast_tanh(v0);
                float hv1 = fast_tanh(v1);
                out[base + ccol]     = hv0;
                out[base + ccol + 1] = hv1;
                __nv_bfloat16 hi, lo;
                split2(hv0, hi, lo);
                g_hh[wb][m * HH + ccol] = hi; g_hl[wb][m * HH + ccol] = lo;
                split2(hv1, hi, lo);
                g_hh[wb][m * HH + ccol + 1] = hi; g_hl[wb][m * HH + ccol + 1] = lo;
            }
        }
        __threadfence();
        grid_barrier();
    }
}

// ---------------- launch ----------------------------------------------------
extern "C" void kernel_launch(void *const *d_in, const int *in_sizes, int n_in,
                              void *d_out, int out_size) {
    const float *x  = (const float *)d_in[0];   // (64, 512, 512)
    const float *h0 = (const float *)d_in[1];   // (64, 512)
    const float *Wx = (const float *)d_in[2];   // (512, 512)
    const float *Wh = (const float *)d_in[3];   // (512, 512)
    const float *b  = (const float *)d_in[4];   // (512,)
    float *out = (float *)d_out;                // (64, 512, 512)

    const int scan_smem = (2 * 64 * HSTRIDE + 2 * SCAN_NT * HSTRIDE) * (int)sizeof(__nv_bfloat16);
    cudaFuncSetAttribute(rnn_scan_kernel, cudaFuncAttributeMaxDynamicSharedMemorySize, scan_smem);

    dim3 grid1(NB * TT / 128, HH / 64);
    gemm_xwx_kernel<<<grid1, 256>>>(x, Wx, b, out);
    rnn_scan_kernel<<<SCAN_CTAS, 256, scan_smem>>>(h0, Wh, out);
}

// round 2
// speedup vs baseline: 1.6727x; 1.6727x over previous
#include <cuda_runtime.h>
#include <cuda_bf16.h>

#define NB 64      // batch
#define TT 512     // timesteps
#define DD 512     // input size
#define HH 512     // hidden size
#define SCAN_CTAS 64
#define SCAN_NT 8              // hidden columns per CTA
#define HSTRIDE 520            // 512 + 8 pad halves (16B-aligned rows, conflict-free LDSM)

// ---------------- scratch (device globals; no allocation allowed) ----------
__device__ __align__(16) __nv_bfloat16 g_hh[2][NB * HH];  // h hi, double buffered
__device__ __align__(16) __nv_bfloat16 g_hl[2][NB * HH];  // h lo
__device__ unsigned g_bar_gen;
__device__ unsigned g_bar_cnt;

// ---------------- helpers --------------------------------------------------
__device__ __forceinline__ void split2(float v, __nv_bfloat16 &hi, __nv_bfloat16 &lo) {
    hi = __float2bfloat16(v);
    lo = __float2bfloat16(v - __bfloat162float(hi));
}

__device__ __forceinline__ void mma4(float *c, unsigned a0, unsigned a1, unsigned a2,
                                     unsigned a3, unsigned b0, unsigned b1) {
    asm volatile(
        "mma.sync.aligned.m16n8k16.row.col.f32.bf16.bf16.f32 "
        "{%0,%1,%2,%3}, {%4,%5,%6,%7}, {%8,%9}, {%0,%1,%2,%3};\n"
        : "+f"(c[0]), "+f"(c[1]), "+f"(c[2]), "+f"(c[3])
        : "r"(a0), "r"(a1), "r"(a2), "r"(a3), "r"(b0), "r"(b1));
}

__device__ __forceinline__ void ldsm_x4(unsigned &r0, unsigned &r1, unsigned &r2,
                                        unsigned &r3, unsigned addr) {
    asm volatile("ldmatrix.sync.aligned.m8n8.x4.shared.b16 {%0,%1,%2,%3}, [%4];"
                 : "=r"(r0), "=r"(r1), "=r"(r2), "=r"(r3)
                 : "r"(addr));
}

__device__ __forceinline__ float fast_tanh(float x) {
    float e = __expf(2.0f * x);
    return 1.0f - __fdividef(2.0f, e + 1.0f);
}

// ---------------- kernel 1: xWx = x @ Wx + b  -> out ------------------------
__global__ __launch_bounds__(256) void gemm_xwx_kernel(
    const float *__restrict__ x, const float *__restrict__ Wx,
    const float *__restrict__ b, float *__restrict__ out) {

    __shared__ __align__(16) __nv_bfloat16 Ah[128 * 40];
    __shared__ __align__(16) __nv_bfloat16 Al[128 * 40];
    __shared__ __align__(16) __nv_bfloat16 Bh[64 * 40];
    __shared__ __align__(16) __nv_bfloat16 Bl[64 * 40];

    const int tid  = threadIdx.x;
    const int warp = tid >> 5;
    const int lane = tid & 31;
    const int g    = lane >> 2;
    const int tg   = lane & 3;
    const int wm   = warp >> 1;
    const int wn   = warp & 1;
    const int row0 = blockIdx.x * 128;
    const int col0 = blockIdx.y * 64;

    float acc[2][4][4];
#pragma unroll
    for (int mt = 0; mt < 2; mt++)
#pragma unroll
        for (int nt = 0; nt < 4; nt++)
#pragma unroll
            for (int i = 0; i < 4; i++) acc[mt][nt][i] = 0.0f;

    for (int k0 = 0; k0 < DD; k0 += 32) {
        __syncthreads();
#pragma unroll
        for (int i = 0; i < 16; i++) {
            int idx = tid + i * 256;
            int r = idx >> 5, c = idx & 31;
            float v = x[(size_t)(row0 + r) * DD + k0 + c];
            __nv_bfloat16 hi, lo; split2(v, hi, lo);
            Ah[r * 40 + c] = hi; Al[r * 40 + c] = lo;
        }
#pragma unroll
        for (int i = 0; i < 8; i++) {
            int idx = tid + i * 256;
            int nn = idx & 63, kk = idx >> 6;
            float v = Wx[(size_t)(k0 + kk) * HH + col0 + nn];
            __nv_bfloat16 hi, lo; split2(v, hi, lo);
            Bh[nn * 40 + kk] = hi; Bl[nn * 40 + kk] = lo;
        }
        __syncthreads();

#pragma unroll
        for (int ks = 0; ks < 2; ks++) {
            const int kb = ks * 16;
            unsigned ah[2][4], al[2][4], bh[4][2], bl[4][2];
#pragma unroll
            for (int mt = 0; mt < 2; mt++) {
                int r = wm * 32 + mt * 16 + g;
                ah[mt][0] = *(const unsigned *)&Ah[r * 40 + kb + tg * 2];
                ah[mt][1] = *(const unsigned *)&Ah[(r + 8) * 40 + kb + tg * 2];
                ah[mt][2] = *(const unsigned *)&Ah[r * 40 + kb + 8 + tg * 2];
                ah[mt][3] = *(const unsigned *)&Ah[(r + 8) * 40 + kb + 8 + tg * 2];
                al[mt][0] = *(const unsigned *)&Al[r * 40 + kb + tg * 2];
                al[mt][1] = *(const unsigned *)&Al[(r + 8) * 40 + kb + tg * 2];
                al[mt][2] = *(const unsigned *)&Al[r * 40 + kb + 8 + tg * 2];
                al[mt][3] = *(const unsigned *)&Al[(r + 8) * 40 + kb + 8 + tg * 2];
            }
#pragma unroll
            for (int nt = 0; nt < 4; nt++) {
                int n = wn * 32 + nt * 8 + g;
                bh[nt][0] = *(const unsigned *)&Bh[n * 40 + kb + tg * 2];
                bh[nt][1] = *(const unsigned *)&Bh[n * 40 + kb + 8 + tg * 2];
                bl[nt][0] = *(const unsigned *)&Bl[n * 40 + kb + tg * 2];
                bl[nt][1] = *(const unsigned *)&Bl[n * 40 + kb + 8 + tg * 2];
            }
#pragma unroll
            for (int mt = 0; mt < 2; mt++)
#pragma unroll
                for (int nt = 0; nt < 4; nt++) {
                    mma4(acc[mt][nt], ah[mt][0], ah[mt][1], ah[mt][2], ah[mt][3], bh[nt][0], bh[nt][1]);
                    mma4(acc[mt][nt], ah[mt][0], ah[mt][1], ah[mt][2], ah[mt][3], bl[nt][0], bl[nt][1]);
                    mma4(acc[mt][nt], al[mt][0], al[mt][1], al[mt][2], al[mt][3], bh[nt][0], bh[nt][1]);
                }
        }
    }

#pragma unroll
    for (int mt = 0; mt < 2; mt++)
#pragma unroll
        for (int nt = 0; nt < 4; nt++) {
            int r = row0 + wm * 32 + mt * 16 + g;
            int c = col0 + wn * 32 + nt * 8 + tg * 2;
            float b0 = b[c], b1 = b[c + 1];
            out[(size_t)r * HH + c]           = acc[mt][nt][0] + b0;
            out[(size_t)r * HH + c + 1]       = acc[mt][nt][1] + b1;
            out[(size_t)(r + 8) * HH + c]     = acc[mt][nt][2] + b0;
            out[(size_t)(r + 8) * HH + c + 1] = acc[mt][nt][3] + b1;
        }
}

// ---------------- barrier reset (per graph replay determinism) --------------
__global__ void reset_bar_kernel() { g_bar_gen = 0; g_bar_cnt = 0; }

// ---------------- one-sided acq/rel grid barrier ----------------------------
__device__ __forceinline__ void grid_barrier(unsigned target) {
    __syncthreads();
    if (threadIdx.x == 0) {
        unsigned *cntp = &g_bar_cnt;
        unsigned *genp = &g_bar_gen;
        unsigned old;
        asm volatile("atom.release.gpu.global.add.u32 %0, [%1], 1;"
                     : "=r"(old) : "l"(cntp) : "memory");
        if (old == SCAN_CTAS - 1) {
            asm volatile("st.relaxed.gpu.global.u32 [%0], 0;" :: "l"(cntp) : "memory");
            asm volatile("st.release.gpu.global.u32 [%0], %1;" :: "l"(genp), "r"(target) : "memory");
        } else {
            unsigned g;
            do {
                asm volatile("ld.acquire.gpu.global.u32 %0, [%1];" : "=r"(g) : "l"(genp) : "memory");
            } while (g < target);
        }
    }
    __syncthreads();
}

// ---------------- kernel 2: persistent recurrent scan -----------------------
// 64 CTAs x 256 threads. CTA owns 8 hidden columns. Warps: 4 m-tiles x 2 K-halves.
__global__ __launch_bounds__(256) void rnn_scan_kernel(
    const float *__restrict__ h0, const float *__restrict__ Wh,
    float *__restrict__ out) {

    extern __shared__ __nv_bfloat16 smem[];
    __nv_bfloat16 *Hh  = smem;                      // 64 x 520
    __nv_bfloat16 *Hl  = Hh + 64 * HSTRIDE;         // 64 x 520
    __nv_bfloat16 *Wsh = Hl + 64 * HSTRIDE;         // 8 x 520
    __nv_bfloat16 *Wsl = Wsh + SCAN_NT * HSTRIDE;   // 8 x 520
    __shared__ float redbuf[4 * 32 * 4];

    const int tid   = threadIdx.x;
    const int warp  = tid >> 5;
    const int lane  = tid & 31;
    const int g     = lane >> 2;
    const int tg    = lane & 3;
    const int cb    = blockIdx.x * SCAN_NT;
    const int mtile = (warp & 3) * 16;
    const int khalf = warp >> 2;        // 0 or 1 (K range khalf*256..+256)
    const int kb    = khalf * 256;      // in halves (= elements)

    // resident Wh slice: Wsh[n][k] = Wh[k][cb+n], split hi/lo
    for (int idx = tid; idx < HH * SCAN_NT; idx += 256) {
        int n = idx & (SCAN_NT - 1), k = idx >> 3;
        float v = Wh[(size_t)k * HH + cb + n];
        __nv_bfloat16 hi, lo; split2(v, hi, lo);
        Wsh[n * HSTRIDE + k] = hi; Wsl[n * HSTRIDE + k] = lo;
    }

    // ldmatrix lane addresses (constant across steps)
    const int quad = lane >> 3, lrow = lane & 7;
    const int aRow = mtile + (quad & 1) * 8 + lrow;
    const int aCol = kb + (quad >> 1) * 8;
    const unsigned addrAh = (unsigned)__cvta_generic_to_shared(Hh + aRow * HSTRIDE + aCol);
    const unsigned addrAl = (unsigned)__cvta_generic_to_shared(Hl + aRow * HSTRIDE + aCol);
    const __nv_bfloat16 *bbase = (quad < 2) ? Wsh : Wsl;
    const unsigned addrB = (unsigned)__cvta_generic_to_shared(
        bbase + lrow * HSTRIDE + kb + (quad & 1) * 8);

    const int ccol = cb + tg * 2;
    const int m0 = mtile + g, m1 = m0 + 8;

    for (int t = 0; t < TT; t++) {
        // ---- stage h_{t-1} into SMEM ----
        if (t == 0) {
#pragma unroll
            for (int i = 0; i < 32; i++) {
                int idx = tid + i * 256;          // 8192 float4 total
                int r = idx >> 7, c4 = idx & 127;
                float4 v = ((const float4 *)(h0 + (size_t)r * HH))[c4];
                __nv_bfloat16 hx, lx, hy, ly, hz, lz, hw, lw;
                split2(v.x, hx, lx); split2(v.y, hy, ly);
                split2(v.z, hz, lz); split2(v.w, hw, lw);
                __nv_bfloat162 ph01 = {hx, hy}, ph23 = {hz, hw};
                __nv_bfloat162 pl01 = {lx, ly}, pl23 = {lz, lw};
                uint2 uh = {*(unsigned *)&ph01, *(unsigned *)&ph23};
                uint2 ul = {*(unsigned *)&pl01, *(unsigned *)&pl23};
                ((uint2 *)(Hh + r * HSTRIDE))[c4] = uh;
                ((uint2 *)(Hl + r * HSTRIDE))[c4] = ul;
            }
        } else {
            const __nv_bfloat16 *sH = g_hh[(t - 1) & 1];
            const __nv_bfloat16 *sL = g_hl[(t - 1) & 1];
#pragma unroll
            for (int i = 0; i < 16; i++) {
                int idx = tid + i * 256;          // 4096 uint4 per buffer
                int r = idx >> 6, c = idx & 63;
                ((uint4 *)(Hh + r * HSTRIDE))[c] = ((const uint4 *)(sH + r * HH))[c];
                ((uint4 *)(Hl + r * HSTRIDE))[c] = ((const uint4 *)(sL + r * HH))[c];
            }
        }

        // ---- prefetch xwx for this step (epilogue warps only) ----
        float2 xw0, xw1;
        if (khalf == 0) {
            xw0 = *(const float2 *)&out[((size_t)m0 * TT + t) * HH + ccol];
            xw1 = *(const float2 *)&out[((size_t)m1 * TT + t) * HH + ccol];
        }
        __syncthreads();

        // ---- k-loop: 16 x k16, split-bf16 3-term ----
        float c4[4] = {0.f, 0.f, 0.f, 0.f};
#pragma unroll
        for (int kk = 0; kk < 16; kk++) {
            const unsigned off = kk * 32;  // 16 halves = 32 bytes
            unsigned a0, a1, a2, a3, l0, l1, l2, l3, b0, b1, b2, b3;
            ldsm_x4(a0, a1, a2, a3, addrAh + off);
            ldsm_x4(l0, l1, l2, l3, addrAl + off);
            ldsm_x4(b0, b1, b2, b3, addrB + off);
            mma4(c4, a0, a1, a2, a3, b0, b1);   // Ah*Bh
            mma4(c4, a0, a1, a2, a3, b2, b3);   // Ah*Bl
            mma4(c4, l0, l1, l2, l3, b0, b1);   // Al*Bh
        }

        // ---- cross-K reduction ----
        if (khalf == 1) {
            float *dst = &redbuf[(warp - 4) * 128 + lane * 4];
            dst[0] = c4[0]; dst[1] = c4[1]; dst[2] = c4[2]; dst[3] = c4[3];
        }
        __syncthreads();

        // ---- epilogue (warps 0-3) ----
        if (khalf == 0) {
            const float *src = &redbuf[warp * 128 + lane * 4];
            float v0 = c4[0] + src[0] + xw0.x;
            float v1 = c4[1] + src[1] + xw0.y;
            float v2 = c4[2] + src[2] + xw1.x;
            float v3 = c4[3] + src[3] + xw1.y;
            float h0v = fast_tanh(v0), h1v = fast_tanh(v1);
            float h2v = fast_tanh(v2), h3v = fast_tanh(v3);

            *(float2 *)&out[((size_t)m0 * TT + t) * HH + ccol] = make_float2(h0v, h1v);
            *(float2 *)&out[((size_t)m1 * TT + t) * HH + ccol] = make_float2(h2v, h3v);

            const int wb = t & 1;
            __nv_bfloat16 hi, lo;
            __nv_bfloat162 ph, pl;
            split2(h0v, hi, lo); ph.x = hi; pl.x = lo;
            split2(h1v, hi, lo); ph.y = hi; pl.y = lo;
            *(unsigned *)&g_hh[wb][m0 * HH + ccol] = *(unsigned *)&ph;
            *(unsigned *)&g_hl[wb][m0 * HH + ccol] = *(unsigned *)&pl;
            split2(h2v, hi, lo); ph.x = hi; pl.x = lo;
            split2(h3v, hi, lo); ph.y = hi; pl.y = lo;
            *(unsigned *)&g_hh[wb][m1 * HH + ccol] = *(unsigned *)&ph;
            *(unsigned *)&g_hl[wb][m1 * HH + ccol] = *(unsigned *)&pl;
        }

        if (t < TT - 1) grid_barrier((unsigned)(t + 1));
    }
}

// ---------------- launch ----------------------------------------------------
extern "C" void kernel_launch(void *const *d_in, const int *in_sizes, int n_in,
                              void *d_out, int out_size) {
    const float *x  = (const float *)d_in[0];   // (64, 512, 512)
    const float *h0 = (const float *)d_in[1];   // (64, 512)
    const float *Wx = (const float *)d_in[2];   // (512, 512)
    const float *Wh = (const float *)d_in[3];   // (512, 512)
    const float *b  = (const float *)d_in[4];   // (512,)
    float *out = (float *)d_out;                // (64, 512, 512)

    const int scan_smem =
        (2 * 64 * HSTRIDE + 2 * SCAN_NT * HSTRIDE) * (int)sizeof(__nv_bfloat16);
    cudaFuncSetAttribute(rnn_scan_kernel,
                         cudaFuncAttributeMaxDynamicSharedMemorySize, scan_smem);

    dim3 grid1(NB * TT / 128, HH / 64);
    gemm_xwx_kernel<<<grid1, 256>>>(x, Wx, b, out);
    reset_bar_kernel<<<1, 1>>>();
    rnn_scan_kernel<<<SCAN_CTAS, 256, scan_smem>>>(h0, Wh, out);
}

// round 3
// speedup vs baseline: 2.2888x; 1.3684x over previous
#include <cuda_runtime.h>
#include <cuda_bf16.h>

#define NB 64      // batch
#define TT 512     // timesteps
#define DD 512     // input size
#define HH 512     // hidden size

#define GROUPS 4           // m-groups (16 batch rows each) -- independent recurrences
#define SUBS 32            // n-CTAs per group
#define SCAN_CTAS (GROUPS * SUBS)   // 128
#define SCAN_NT 16         // hidden columns per CTA
#define MROWS 16           // batch rows per group
#define HSTRIDE 520        // 512 + 8 pad halves (16B-aligned rows, conflict-free LDSM)

// ---------------- scratch (device globals; no allocation allowed) ----------
__device__ __align__(16) __nv_bfloat16 g_hh[2][NB * HH];  // h hi, double buffered
__device__ __align__(16) __nv_bfloat16 g_hl[2][NB * HH];  // h lo
__device__ unsigned g_bar_gen[GROUPS];
__device__ unsigned g_bar_cnt[GROUPS];

// ---------------- helpers --------------------------------------------------
__device__ __forceinline__ void split2(float v, __nv_bfloat16 &hi, __nv_bfloat16 &lo) {
    hi = __float2bfloat16(v);
    lo = __float2bfloat16(v - __bfloat162float(hi));
}

__device__ __forceinline__ void mma4(float *c, unsigned a0, unsigned a1, unsigned a2,
                                     unsigned a3, unsigned b0, unsigned b1) {
    asm volatile(
        "mma.sync.aligned.m16n8k16.row.col.f32.bf16.bf16.f32 "
        "{%0,%1,%2,%3}, {%4,%5,%6,%7}, {%8,%9}, {%0,%1,%2,%3};\n"
        : "+f"(c[0]), "+f"(c[1]), "+f"(c[2]), "+f"(c[3])
        : "r"(a0), "r"(a1), "r"(a2), "r"(a3), "r"(b0), "r"(b1));
}

__device__ __forceinline__ void ldsm_x4(unsigned &r0, unsigned &r1, unsigned &r2,
                                        unsigned &r3, unsigned addr) {
    asm volatile("ldmatrix.sync.aligned.m8n8.x4.shared.b16 {%0,%1,%2,%3}, [%4];"
                 : "=r"(r0), "=r"(r1), "=r"(r2), "=r"(r3)
                 : "r"(addr));
}

__device__ __forceinline__ void cp16(void *dst_smem, const void *src) {
    unsigned d = (unsigned)__cvta_generic_to_shared(dst_smem);
    asm volatile("cp.async.cg.shared.global [%0], [%1], 16;" :: "r"(d), "l"(src));
}

__device__ __forceinline__ float fast_tanh(float x) {
    float e = __expf(2.0f * x);
    return 1.0f - __fdividef(2.0f, e + 1.0f);
}

// ---------------- kernel 1: xWx = x @ Wx + b  -> out ------------------------
__global__ __launch_bounds__(256) void gemm_xwx_kernel(
    const float *__restrict__ x, const float *__restrict__ Wx,
    const float *__restrict__ b, float *__restrict__ out) {

    __shared__ __align__(16) __nv_bfloat16 Ah[128 * 40];
    __shared__ __align__(16) __nv_bfloat16 Al[128 * 40];
    __shared__ __align__(16) __nv_bfloat16 Bh[64 * 40];
    __shared__ __align__(16) __nv_bfloat16 Bl[64 * 40];

    const int tid  = threadIdx.x;
    const int warp = tid >> 5;
    const int lane = tid & 31;
    const int g    = lane >> 2;
    const int tg   = lane & 3;
    const int wm   = warp >> 1;
    const int wn   = warp & 1;
    const int row0 = blockIdx.x * 128;
    const int col0 = blockIdx.y * 64;

    float acc[2][4][4];
#pragma unroll
    for (int mt = 0; mt < 2; mt++)
#pragma unroll
        for (int nt = 0; nt < 4; nt++)
#pragma unroll
            for (int i = 0; i < 4; i++) acc[mt][nt][i] = 0.0f;

    for (int k0 = 0; k0 < DD; k0 += 32) {
        __syncthreads();
#pragma unroll
        for (int i = 0; i < 16; i++) {
            int idx = tid + i * 256;
            int r = idx >> 5, c = idx & 31;
            float v = x[(size_t)(row0 + r) * DD + k0 + c];
            __nv_bfloat16 hi, lo; split2(v, hi, lo);
            Ah[r * 40 + c] = hi; Al[r * 40 + c] = lo;
        }
#pragma unroll
        for (int i = 0; i < 8; i++) {
            int idx = tid + i * 256;
            int nn = idx & 63, kk = idx >> 6;
            float v = Wx[(size_t)(k0 + kk) * HH + col0 + nn];
            __nv_bfloat16 hi, lo; split2(v, hi, lo);
            Bh[nn * 40 + kk] = hi; Bl[nn * 40 + kk] = lo;
        }
        __syncthreads();

#pragma unroll
        for (int ks = 0; ks < 2; ks++) {
            const int kb = ks * 16;
            unsigned ah[2][4], al[2][4], bh[4][2], bl[4][2];
#pragma unroll
            for (int mt = 0; mt < 2; mt++) {
                int r = wm * 32 + mt * 16 + g;
                ah[mt][0] = *(const unsigned *)&Ah[r * 40 + kb + tg * 2];
                ah[mt][1] = *(const unsigned *)&Ah[(r + 8) * 40 + kb + tg * 2];
                ah[mt][2] = *(const unsigned *)&Ah[r * 40 + kb + 8 + tg * 2];
                ah[mt][3] = *(const unsigned *)&Ah[(r + 8) * 40 + kb + 8 + tg * 2];
                al[mt][0] = *(const unsigned *)&Al[r * 40 + kb + tg * 2];
                al[mt][1] = *(const unsigned *)&Al[(r + 8) * 40 + kb + tg * 2];
                al[mt][2] = *(const unsigned *)&Al[r * 40 + kb + 8 + tg * 2];
                al[mt][3] = *(const unsigned *)&Al[(r + 8) * 40 + kb + 8 + tg * 2];
            }
#pragma unroll
            for (int nt = 0; nt < 4; nt++) {
                int n = wn * 32 + nt * 8 + g;
                bh[nt][0] = *(const unsigned *)&Bh[n * 40 + kb + tg * 2];
                bh[nt][1] = *(const unsigned *)&Bh[n * 40 + kb + 8 + tg * 2];
                bl[nt][0] = *(const unsigned *)&Bl[n * 40 + kb + tg * 2];
                bl[nt][1] = *(const unsigned *)&Bl[n * 40 + kb + 8 + tg * 2];
            }
#pragma unroll
            for (int mt = 0; mt < 2; mt++)
#pragma unroll
                for (int nt = 0; nt < 4; nt++) {
                    mma4(acc[mt][nt], ah[mt][0], ah[mt][1], ah[mt][2], ah[mt][3], bh[nt][0], bh[nt][1]);
                    mma4(acc[mt][nt], ah[mt][0], ah[mt][1], ah[mt][2], ah[mt][3], bl[nt][0], bl[nt][1]);
                    mma4(acc[mt][nt], al[mt][0], al[mt][1], al[mt][2], al[mt][3], bh[nt][0], bh[nt][1]);
                }
        }
    }

#pragma unroll
    for (int mt = 0; mt < 2; mt++)
#pragma unroll
        for (int nt = 0; nt < 4; nt++) {
            int r = row0 + wm * 32 + mt * 16 + g;
            int c = col0 + wn * 32 + nt * 8 + tg * 2;
            float b0 = b[c], b1 = b[c + 1];
            out[(size_t)r * HH + c]           = acc[mt][nt][0] + b0;
            out[(size_t)r * HH + c + 1]       = acc[mt][nt][1] + b1;
            out[(size_t)(r + 8) * HH + c]     = acc[mt][nt][2] + b0;
            out[(size_t)(r + 8) * HH + c + 1] = acc[mt][nt][3] + b1;
        }
}

// ---------------- barrier reset (per graph replay determinism) --------------
__global__ void reset_bar_kernel() {
    if (threadIdx.x < GROUPS) {
        g_bar_gen[threadIdx.x] = 0;
        g_bar_cnt[threadIdx.x] = 0;
    }
}

// ---------------- one-sided acq/rel per-group barrier -----------------------
__device__ __forceinline__ void group_barrier(int group, unsigned target) {
    __syncthreads();
    if (threadIdx.x == 0) {
        unsigned *cntp = &g_bar_cnt[group];
        unsigned *genp = &g_bar_gen[group];
        unsigned old;
        asm volatile("atom.release.gpu.global.add.u32 %0, [%1], 1;"
                     : "=r"(old) : "l"(cntp) : "memory");
        if (old == SUBS - 1) {
            asm volatile("st.relaxed.gpu.global.u32 [%0], 0;" :: "l"(cntp) : "memory");
            asm volatile("st.release.gpu.global.u32 [%0], %1;" :: "l"(genp), "r"(target) : "memory");
        } else {
            unsigned g;
            do {
                asm volatile("ld.acquire.gpu.global.u32 %0, [%1];" : "=r"(g) : "l"(genp) : "memory");
            } while (g < target);
        }
    }
    __syncthreads();
}

// ---------------- kernel 2: persistent recurrent scan -----------------------
// 128 CTAs = 4 independent m-groups (16 batch rows) x 32 n-CTAs (16 cols).
// 8 warps per CTA: 4 K-quarters (K=128) x 2 n-tiles (n8). Per-step h traffic
// per CTA: only its group's 16 rows (32 KB hi+lo) via cp.async.
__global__ __launch_bounds__(256) void rnn_scan_kernel(
    const float *__restrict__ h0, const float *__restrict__ Wh,
    float *__restrict__ out) {

    extern __shared__ __nv_bfloat16 smem[];
    __nv_bfloat16 *Hh  = smem;                        // 16 x 520
    __nv_bfloat16 *Hl  = Hh + MROWS * HSTRIDE;        // 16 x 520
    __nv_bfloat16 *Wsh = Hl + MROWS * HSTRIDE;        // 16 x 520
    __nv_bfloat16 *Wsl = Wsh + SCAN_NT * HSTRIDE;     // 16 x 520
    __shared__ float redbuf[6 * 128];                 // 3 k-partials x 2 ntiles

    const int tid   = threadIdx.x;
    const int warp  = tid >> 5;
    const int lane  = tid & 31;
    const int g     = lane >> 2;
    const int tg    = lane & 3;
    const int group = blockIdx.x >> 5;
    const int sub   = blockIdx.x & 31;
    const int cb    = sub * SCAN_NT;
    const int rbase = group * MROWS;
    const int kq    = warp >> 1;        // K-quarter 0..3
    const int ntile = warp & 1;         // n8 tile 0..1
    const int kb    = kq * 128;         // K offset in elements

    // resident Wh slice: Wsh[n][k] = Wh[k][cb+n], split hi/lo
    for (int idx = tid; idx < HH * SCAN_NT; idx += 256) {
        int n = idx & (SCAN_NT - 1), k = idx >> 4;
        float v = Wh[(size_t)k * HH + cb + n];
        __nv_bfloat16 hi, lo; split2(v, hi, lo);
        Wsh[n * HSTRIDE + k] = hi; Wsl[n * HSTRIDE + k] = lo;
    }

    // ldmatrix lane addresses (constant across steps)
    const int quad = lane >> 3, lrow = lane & 7;
    const int aRow = (quad & 1) * 8 + lrow;
    const int aCol = kb + (quad >> 1) * 8;
    const unsigned addrAh = (unsigned)__cvta_generic_to_shared(Hh + aRow * HSTRIDE + aCol);
    const unsigned addrAl = (unsigned)__cvta_generic_to_shared(Hl + aRow * HSTRIDE + aCol);
    const __nv_bfloat16 *bbase = (quad < 2) ? Wsh : Wsl;
    const unsigned addrB = (unsigned)__cvta_generic_to_shared(
        bbase + (ntile * 8 + lrow) * HSTRIDE + kb + (quad & 1) * 8);

    const int ccol = cb + ntile * 8 + tg * 2;
    const int m0 = rbase + g, m1 = rbase + g + 8;

    for (int t = 0; t < TT; t++) {
        // ---- prefetch xwx for this step (independent of dataflow) ----
        float2 xw0, xw1;
        if (kq == 0) {
            xw0 = *(const float2 *)&out[((size_t)m0 * TT + t) * HH + ccol];
            xw1 = *(const float2 *)&out[((size_t)m1 * TT + t) * HH + ccol];
        }

        // ---- stage this group's 16 h rows into SMEM ----
        if (t == 0) {
#pragma unroll
            for (int i = 0; i < 8; i++) {
                int idx = tid + i * 256;          // 2048 float4
                int r = idx >> 7, c4 = idx & 127;
                float4 v = ((const float4 *)(h0 + (size_t)(rbase + r) * HH))[c4];
                __nv_bfloat16 hx, lx, hy, ly, hz, lz, hw, lw;
                split2(v.x, hx, lx); split2(v.y, hy, ly);
                split2(v.z, hz, lz); split2(v.w, hw, lw);
                __nv_bfloat162 ph01 = {hx, hy}, ph23 = {hz, hw};
                __nv_bfloat162 pl01 = {lx, ly}, pl23 = {lz, lw};
                uint2 uh = {*(unsigned *)&ph01, *(unsigned *)&ph23};
                uint2 ul = {*(unsigned *)&pl01, *(unsigned *)&pl23};
                ((uint2 *)(Hh + r * HSTRIDE))[c4] = uh;
                ((uint2 *)(Hl + r * HSTRIDE))[c4] = ul;
            }
        } else {
            const __nv_bfloat16 *sH = g_hh[(t - 1) & 1] + (size_t)rbase * HH;
            const __nv_bfloat16 *sL = g_hl[(t - 1) & 1] + (size_t)rbase * HH;
#pragma unroll
            for (int i = 0; i < 4; i++) {
                int idx = tid + i * 256;          // 1024 x 16B per buffer
                int r = idx >> 6, c = idx & 63;
                cp16(Hh + r * HSTRIDE + c * 8, sH + r * HH + c * 8);
            }
#pragma unroll
            for (int i = 0; i < 4; i++) {
                int idx = tid + i * 256;
                int r = idx >> 6, c = idx & 63;
                cp16(Hl + r * HSTRIDE + c * 8, sL + r * HH + c * 8);
            }
            asm volatile("cp.async.commit_group;");
            asm volatile("cp.async.wait_group 0;");
        }
        __syncthreads();

        // ---- k-loop: 8 x k16 per warp, split-bf16 3-term ----
        float c4[4] = {0.f, 0.f, 0.f, 0.f};
#pragma unroll
        for (int kk = 0; kk < 8; kk++) {
            const unsigned off = kk * 32;  // 16 halves = 32 bytes
            unsigned a0, a1, a2, a3, l0, l1, l2, l3, b0, b1, b2, b3;
            ldsm_x4(a0, a1, a2, a3, addrAh + off);
            ldsm_x4(l0, l1, l2, l3, addrAl + off);
            ldsm_x4(b0, b1, b2, b3, addrB + off);
            mma4(c4, a0, a1, a2, a3, b0, b1);   // Ah*Bh
            mma4(c4, a0, a1, a2, a3, b2, b3);   // Ah*Bl
            mma4(c4, l0, l1, l2, l3, b0, b1);   // Al*Bh
        }

        // ---- cross-K reduction (kq 1..3 -> redbuf) ----
        if (kq > 0) {
            float *dst = &redbuf[((kq - 1) * 2 + ntile) * 128 + lane * 4];
            dst[0] = c4[0]; dst[1] = c4[1]; dst[2] = c4[2]; dst[3] = c4[3];
        }
        __syncthreads();

        // ---- epilogue (kq==0 warps) ----
        if (kq == 0) {
            float v0 = c4[0], v1 = c4[1], v2 = c4[2], v3 = c4[3];
#pragma unroll
            for (int j = 0; j < 3; j++) {
                const float *src = &redbuf[(j * 2 + ntile) * 128 + lane * 4];
                v0 += src[0]; v1 += src[1]; v2 += src[2]; v3 += src[3];
            }
            v0 += xw0.x; v1 += xw0.y; v2 += xw1.x; v3 += xw1.y;
            float h0v = fast_tanh(v0), h1v = fast_tanh(v1);
            float h2v = fast_tanh(v2), h3v = fast_tanh(v3);

            *(float2 *)&out[((size_t)m0 * TT + t) * HH + ccol] = make_float2(h0v, h1v);
            *(float2 *)&out[((size_t)m1 * TT + t) * HH + ccol] = make_float2(h2v, h3v);

            const int wb = t & 1;
            __nv_bfloat16 hi, lo;
            __nv_bfloat162 ph, pl;
            split2(h0v, hi, lo); ph.x = hi; pl.x = lo;
            split2(h1v, hi, lo); ph.y = hi; pl.y = lo;
            *(unsigned *)&g_hh[wb][m0 * HH + ccol] = *(unsigned *)&ph;
            *(unsigned *)&g_hl[wb][m0 * HH + ccol] = *(unsigned *)&pl;
            split2(h2v, hi, lo); ph.x = hi; pl.x = lo;
            split2(h3v, hi, lo); ph.y = hi; pl.y = lo;
            *(unsigned *)&g_hh[wb][m1 * HH + ccol] = *(unsigned *)&ph;
            *(unsigned *)&g_hl[wb][m1 * HH + ccol] = *(unsigned *)&pl;
        }

        if (t < TT - 1) group_barrier(group, (unsigned)(t + 1));
    }
}

// ---------------- launch ----------------------------------------------------
extern "C" void kernel_launch(void *const *d_in, const int *in_sizes, int n_in,
                              void *d_out, int out_size) {
    const float *x  = (const float *)d_in[0];   // (64, 512, 512)
    const float *h0 = (const float *)d_in[1];   // (64, 512)
    const float *Wx = (const float *)d_in[2];   // (512, 512)
    const float *Wh = (const float *)d_in[3];   // (512, 512)
    const float *b  = (const float *)d_in[4];   // (512,)
    float *out = (float *)d_out;                // (64, 512, 512)

    const int scan_smem =
        (2 * MROWS * HSTRIDE + 2 * SCAN_NT * HSTRIDE) * (int)sizeof(__nv_bfloat16);
    cudaFuncSetAttribute(rnn_scan_kernel,
                         cudaFuncAttributeMaxDynamicSharedMemorySize, scan_smem);

    dim3 grid1(NB * TT / 128, HH / 64);
    gemm_xwx_kernel<<<grid1, 256>>>(x, Wx, b, out);
    reset_bar_kernel<<<1, 32>>>();
    rnn_scan_kernel<<<SCAN_CTAS, 256, scan_smem>>>(h0, Wh, out);
}